// round 13
// baseline (speedup 1.0000x reference)
#include <cuda_runtime.h>

namespace {
constexpr int NX = 256, NY = 256, NZ = 128;
constexpr int NZ4 = NZ / 4, XS4 = NY * NZ4, FS4 = NX * XS4;

constexpr float CVc = 717.0f;
constexpr float MUc = 1.8e-5f, KTHc = 0.025f, Gc = 9.8f;
constexpr float Rg  = 287.0f;

constexpr double DXd = 1.0 / NX, DYd = 1.0 / NY, DZd = 1.0 / (NZ - 1);
constexpr float inv2dx = (float)(0.5 / DXd);
constexpr float inv2dy = (float)(0.5 / DYd);
constexpr float inv2dz = (float)(0.5 / DZd);
constexpr float invdx2 = (float)(1.0 / (DXd * DXd));
constexpr float invdy2 = (float)(1.0 / (DYd * DYd));
constexpr float invdz2 = (float)(1.0 / (DZd * DZd));
constexpr float kTco   = KTHc / CVc;

__device__ __forceinline__ float4 operator+(float4 a, float4 b){ return make_float4(a.x+b.x, a.y+b.y, a.z+b.z, a.w+b.w); }
__device__ __forceinline__ float4 operator-(float4 a, float4 b){ return make_float4(a.x-b.x, a.y-b.y, a.z-b.z, a.w-b.w); }
__device__ __forceinline__ float4 operator*(float4 a, float4 b){ return make_float4(a.x*b.x, a.y*b.y, a.z*b.z, a.w*b.w); }
__device__ __forceinline__ float4 operator*(float4 a, float s){ return make_float4(a.x*s, a.y*s, a.z*s, a.w*s); }
__device__ __forceinline__ float4 operator*(float s, float4 a){ return a * s; }

__device__ __forceinline__ float4 zm_of(float4 a){
    float p = __shfl_up_sync(0xffffffffu, a.w, 1);
    return make_float4(p, a.x, a.y, a.z);
}
__device__ __forceinline__ float4 zp_of(float4 a){
    float n = __shfl_down_sync(0xffffffffu, a.x, 1);
    return make_float4(a.y, a.z, a.w, n);
}
__device__ __forceinline__ float4 inv4(float4 a){
    return make_float4(1.0f/a.x, 1.0f/a.y, 1.0f/a.z, 1.0f/a.w);
}
__device__ __forceinline__ float4 maskwall(float4 v, bool lo, bool hi){
    if (lo) v.x = 0.0f;
    if (hi) v.w = 0.0f;
    return v;
}

__global__ __launch_bounds__(256, 2)
void rby2w_kernel(const float4* __restrict__ s, float4* __restrict__ o)
{
    const int lane = threadIdx.x;                       // z chunk (4 z per lane)
    const int ty   = threadIdx.y;                       // 0..7 (each owns a y-pair)
    const int y0   = (blockIdx.x << 4) + (ty << 1);     // 16 y rows per block
    const int y1   = y0 + 1;
    const int x    = blockIdx.y;

    const int pxm = ((x + NX - 1) & (NX - 1)) * XS4;
    const int pc  = x * XS4;
    const int pxp = ((x + 1) & (NX - 1)) * XS4;

    const int iym  = pc + ((y0 + NY - 1) & (NY - 1)) * NZ4 + lane;
    const int i0   = pc + y0 * NZ4 + lane;
    const int i1   = pc + y1 * NZ4 + lane;
    const int iyp  = pc + ((y1 + 1) & (NY - 1)) * NZ4 + lane;
    const int ixm0 = pxm + y0 * NZ4 + lane;
    const int ixm1 = pxm + y1 * NZ4 + lane;
    const int ixp0 = pxp + y0 * NZ4 + lane;
    const int ixp1 = pxp + y1 * NZ4 + lane;

    const bool lo = (lane == 0);
    const bool hi = (lane == 31);

    float4 rinv0, rinv1;
    float4 dpdx0, dpdx1, dpdy0, dpdy1, dpdz0, dpdz1;
    float4 uxm0, uxm1, uxp0, uxp1;          // kept for u phase
    float4 uc0, uc1, vc0, vc1, wc0, wc1;    // advection velocities

    // ========= phase 1: rho + T -> rinv, pressure gradients, drou, dT =========
    {
        const float4 rym = s[3*FS4+iym], r0 = s[3*FS4+i0], r1 = s[3*FS4+i1], ryp = s[3*FS4+iyp];
        const float4 rxm0 = s[3*FS4+ixm0], rxm1 = s[3*FS4+ixm1];
        const float4 rxp0 = s[3*FS4+ixp0], rxp1 = s[3*FS4+ixp1];
        const float4 Tym = s[4*FS4+iym], T0 = s[4*FS4+i0], T1 = s[4*FS4+i1], Typ = s[4*FS4+iyp];
        const float4 Txm0 = s[4*FS4+ixm0], Txm1 = s[4*FS4+ixm1];
        const float4 Txp0 = s[4*FS4+ixp0], Txp1 = s[4*FS4+ixp1];

        rinv0 = inv4(r0);
        rinv1 = inv4(r1);

        dpdx0 = (rxp0 * Txp0 - rxm0 * Txm0) * (Rg * inv2dx);
        dpdx1 = (rxp1 * Txp1 - rxm1 * Txm1) * (Rg * inv2dx);
        dpdy0 = (r1  * T1  - rym * Tym) * (Rg * inv2dy);
        dpdy1 = (ryp * Typ - r0  * T0 ) * (Rg * inv2dy);
        const float4 p0 = r0 * T0;
        const float4 p1 = r1 * T1;
        dpdz0 = (zp_of(p0) - zm_of(p0)) * (Rg * inv2dz);
        dpdz1 = (zp_of(p1) - zm_of(p1)) * (Rg * inv2dz);

        // u x-neighbors for drou (kept live into the u phase)
        uxm0 = s[0*FS4+ixm0]; uxm1 = s[0*FS4+ixm1];
        uxp0 = s[0*FS4+ixp0]; uxp1 = s[0*FS4+ixp1];
        __stcs(&o[3*FS4 + i0], (rxm0 * uxm0 - rxp0 * uxp0) * inv2dx);
        __stcs(&o[3*FS4 + i1], (rxm1 * uxm1 - rxp1 * uxp1) * inv2dx);

        // advection velocities (centers)
        uc0 = s[0*FS4+i0]; uc1 = s[0*FS4+i1];
        vc0 = s[1*FS4+i0]; vc1 = s[1*FS4+i1];
        wc0 = s[2*FS4+i0]; wc1 = s[2*FS4+i1];

        // dT (T fully resident)
        const float4 Tzm0 = zm_of(T0), Tzp0 = zp_of(T0);
        const float4 Tzm1 = zm_of(T1), Tzp1 = zp_of(T1);

        const float4 lapT0 = (Txp0 + Txm0 - T0*2.0f)*invdx2 + (T1 + Tym - T0*2.0f)*invdy2 + (Tzp0 + Tzm0 - T0*2.0f)*invdz2;
        const float4 advT0 = uc0*((Txp0 - Txm0)*inv2dx) + vc0*((T1 - Tym)*inv2dy) + wc0*((Tzp0 - Tzm0)*inv2dz);
        __stcs(&o[4*FS4 + i0], maskwall((lapT0 * kTco) * rinv0 - advT0, lo, hi));

        const float4 lapT1 = (Txp1 + Txm1 - T1*2.0f)*invdx2 + (Typ + T0 - T1*2.0f)*invdy2 + (Tzp1 + Tzm1 - T1*2.0f)*invdz2;
        const float4 advT1 = uc1*((Txp1 - Txm1)*inv2dx) + vc1*((Typ - T0)*inv2dy) + wc1*((Tzp1 - Tzm1)*inv2dz);
        __stcs(&o[4*FS4 + i1], maskwall((lapT1 * kTco) * rinv1 - advT1, lo, hi));
    }

    // ========= phase 2: u (x-neighbors already live; y-halo 2 loads) =========
    {
        const float4 uym = s[0*FS4+iym], uyp = s[0*FS4+iyp];
        const float4 uzm0 = zm_of(uc0), uzp0 = zp_of(uc0);
        const float4 uzm1 = zm_of(uc1), uzp1 = zp_of(uc1);

        const float4 lapU0 = (uxp0 + uxm0 - uc0*2.0f)*invdx2 + (uc1 + uym - uc0*2.0f)*invdy2 + (uzp0 + uzm0 - uc0*2.0f)*invdz2;
        const float4 advU0 = uc0*((uxp0 - uxm0)*inv2dx) + vc0*((uc1 - uym)*inv2dy) + wc0*((uzp0 - uzm0)*inv2dz);
        __stcs(&o[0*FS4 + i0], maskwall((lapU0 * MUc - dpdx0) * rinv0 - advU0, lo, hi));

        const float4 lapU1 = (uxp1 + uxm1 - uc1*2.0f)*invdx2 + (uyp + uc0 - uc1*2.0f)*invdy2 + (uzp1 + uzm1 - uc1*2.0f)*invdz2;
        const float4 advU1 = uc1*((uxp1 - uxm1)*inv2dx) + vc1*((uyp - uc0)*inv2dy) + wc1*((uzp1 - uzm1)*inv2dz);
        __stcs(&o[0*FS4 + i1], maskwall((lapU1 * MUc - dpdx1) * rinv1 - advU1, lo, hi));
    }

    // ========= phase 3: v =========
    {
        const float4 vym = s[1*FS4+iym], vyp = s[1*FS4+iyp];
        const float4 vxm0 = s[1*FS4+ixm0], vxm1 = s[1*FS4+ixm1];
        const float4 vxp0 = s[1*FS4+ixp0], vxp1 = s[1*FS4+ixp1];
        const float4 vzm0 = zm_of(vc0), vzp0 = zp_of(vc0);
        const float4 vzm1 = zm_of(vc1), vzp1 = zp_of(vc1);

        const float4 lapV0 = (vxp0 + vxm0 - vc0*2.0f)*invdx2 + (vc1 + vym - vc0*2.0f)*invdy2 + (vzp0 + vzm0 - vc0*2.0f)*invdz2;
        const float4 advV0 = uc0*((vxp0 - vxm0)*inv2dx) + vc0*((vc1 - vym)*inv2dy) + wc0*((vzp0 - vzm0)*inv2dz);
        __stcs(&o[1*FS4 + i0], maskwall((lapV0 * MUc - dpdy0) * rinv0 - advV0, lo, hi));

        const float4 lapV1 = (vxp1 + vxm1 - vc1*2.0f)*invdx2 + (vyp + vc0 - vc1*2.0f)*invdy2 + (vzp1 + vzm1 - vc1*2.0f)*invdz2;
        const float4 advV1 = uc1*((vxp1 - vxm1)*inv2dx) + vc1*((vyp - vc0)*inv2dy) + wc1*((vzp1 - vzm1)*inv2dz);
        __stcs(&o[1*FS4 + i1], maskwall((lapV1 * MUc - dpdy1) * rinv1 - advV1, lo, hi));
    }

    // ========= phase 4: w  ((-G*rho)/rho == -G) =========
    {
        const float4 wym = s[2*FS4+iym], wyp = s[2*FS4+iyp];
        const float4 wxm0 = s[2*FS4+ixm0], wxm1 = s[2*FS4+ixm1];
        const float4 wxp0 = s[2*FS4+ixp0], wxp1 = s[2*FS4+ixp1];
        const float4 wzm0 = zm_of(wc0), wzp0 = zp_of(wc0);
        const float4 wzm1 = zm_of(wc1), wzp1 = zp_of(wc1);

        const float4 lapW0 = (wxp0 + wxm0 - wc0*2.0f)*invdx2 + (wc1 + wym - wc0*2.0f)*invdy2 + (wzp0 + wzm0 - wc0*2.0f)*invdz2;
        const float4 advW0 = uc0*((wxp0 - wxm0)*inv2dx) + vc0*((wc1 - wym)*inv2dy) + wc0*((wzp0 - wzm0)*inv2dz);
        float4 dw0 = (lapW0 * MUc - dpdz0) * rinv0 - advW0;
        dw0 = make_float4(dw0.x - Gc, dw0.y - Gc, dw0.z - Gc, dw0.w - Gc);
        __stcs(&o[2*FS4 + i0], maskwall(dw0, lo, hi));

        const float4 lapW1 = (wxp1 + wxm1 - wc1*2.0f)*invdx2 + (wyp + wc0 - wc1*2.0f)*invdy2 + (wzp1 + wzm1 - wc1*2.0f)*invdz2;
        const float4 advW1 = uc1*((wxp1 - wxm1)*inv2dx) + vc1*((wyp - wc0)*inv2dy) + wc1*((wzp1 - wzm1)*inv2dz);
        float4 dw1 = (lapW1 * MUc - dpdz1) * rinv1 - advW1;
        dw1 = make_float4(dw1.x - Gc, dw1.y - Gc, dw1.z - Gc, dw1.w - Gc);
        __stcs(&o[2*FS4 + i1], maskwall(dw1, lo, hi));
    }

    // ========= phase 5: c (one-sided z at walls, NOT masked) =========
    {
        const float4 cym = s[5*FS4+iym], c0 = s[5*FS4+i0], c1 = s[5*FS4+i1], cyp = s[5*FS4+iyp];
        const float4 cxm0 = s[5*FS4+ixm0], cxm1 = s[5*FS4+ixm1];
        const float4 cxp0 = s[5*FS4+ixp0], cxp1 = s[5*FS4+ixp1];

        const float4 czm0 = zm_of(c0), czp0 = zp_of(c0);
        const float4 czm1 = zm_of(c1), czp1 = zp_of(c1);

        float4 dcdz0 = (czp0 - czm0) * inv2dz;
        float4 dcdz1 = (czp1 - czm1) * inv2dz;
        if (lo) {
            dcdz0.x = (-3.0f * c0.x + 4.0f * c0.y - c0.z) * inv2dz;
            dcdz1.x = (-3.0f * c1.x + 4.0f * c1.y - c1.z) * inv2dz;
        }
        if (hi) {
            dcdz0.w = ( 3.0f * c0.w - 4.0f * c0.z + c0.y) * inv2dz;
            dcdz1.w = ( 3.0f * c1.w - 4.0f * c1.z + c1.y) * inv2dz;
        }

        const float4 advC0 = uc0*((cxp0 - cxm0)*inv2dx) + vc0*((c1 - cym)*inv2dy) + wc0*dcdz0;
        __stcs(&o[5*FS4 + i0], make_float4(-advC0.x, -advC0.y, -advC0.z, -advC0.w));
        const float4 advC1 = uc1*((cxp1 - cxm1)*inv2dx) + vc1*((cyp - c0)*inv2dy) + wc1*dcdz1;
        __stcs(&o[5*FS4 + i1], make_float4(-advC1.x, -advC1.y, -advC1.z, -advC1.w));
    }
}
} // namespace

extern "C" void kernel_launch(void* const* d_in, const int* in_sizes, int n_in,
                              void* d_out, int out_size)
{
    const float4* s = (const float4*)d_in[0];
    float4* o = (float4*)d_out;
    dim3 block(32, 8, 1);               // 256 threads: 32 z-chunks × 8 y-pairs (16 rows)
    dim3 grid(NY / 16, NX, 1);          // 16 × 256 blocks
    rby2w_kernel<<<grid, block>>>(s, o);
}

// round 15
// speedup vs baseline: 1.0267x; 1.0267x over previous
#include <cuda_runtime.h>

namespace {
constexpr int NX = 256, NY = 256, NZ = 128;
constexpr int NZ4 = NZ / 4, XS4 = NY * NZ4, FS4 = NX * XS4;

constexpr float CVc = 717.0f;
constexpr float MUc = 1.8e-5f, KTHc = 0.025f, Gc = 9.8f;
constexpr float Rg  = 287.0f;

constexpr double DXd = 1.0 / NX, DYd = 1.0 / NY, DZd = 1.0 / (NZ - 1);
constexpr float inv2dx = (float)(0.5 / DXd);
constexpr float inv2dy = (float)(0.5 / DYd);
constexpr float inv2dz = (float)(0.5 / DZd);
constexpr float invdx2 = (float)(1.0 / (DXd * DXd));
constexpr float invdy2 = (float)(1.0 / (DYd * DYd));
constexpr float invdz2 = (float)(1.0 / (DZd * DZd));
constexpr float kTco   = KTHc / CVc;

__device__ __forceinline__ float4 operator+(float4 a, float4 b){ return make_float4(a.x+b.x, a.y+b.y, a.z+b.z, a.w+b.w); }
__device__ __forceinline__ float4 operator-(float4 a, float4 b){ return make_float4(a.x-b.x, a.y-b.y, a.z-b.z, a.w-b.w); }
__device__ __forceinline__ float4 operator*(float4 a, float4 b){ return make_float4(a.x*b.x, a.y*b.y, a.z*b.z, a.w*b.w); }
__device__ __forceinline__ float4 operator*(float4 a, float s){ return make_float4(a.x*s, a.y*s, a.z*s, a.w*s); }
__device__ __forceinline__ float4 operator*(float s, float4 a){ return a * s; }

// L2 evict_last policy (created once per thread; uniform)
__device__ __forceinline__ unsigned long long mk_policy(){
    unsigned long long pol;
    asm("createpolicy.fractional.L2::evict_last.b64 %0, 1.0;" : "=l"(pol));
    return pol;
}
// input load: non-coherent, L2 evict_last via cache_hint (retain input lines in L2)
__device__ __forceinline__ float4 ldg_el(const float4* p, unsigned long long pol){
    float4 v;
    asm volatile("ld.global.nc.L2::cache_hint.v4.f32 {%0,%1,%2,%3}, [%4], %5;"
                 : "=f"(v.x), "=f"(v.y), "=f"(v.z), "=f"(v.w) : "l"(p), "l"(pol));
    return v;
}

__device__ __forceinline__ float4 zm_of(float4 a){
    float p = __shfl_up_sync(0xffffffffu, a.w, 1);
    return make_float4(p, a.x, a.y, a.z);
}
__device__ __forceinline__ float4 zp_of(float4 a){
    float n = __shfl_down_sync(0xffffffffu, a.x, 1);
    return make_float4(a.y, a.z, a.w, n);
}
__device__ __forceinline__ float4 inv4(float4 a){
    return make_float4(1.0f/a.x, 1.0f/a.y, 1.0f/a.z, 1.0f/a.w);
}
__device__ __forceinline__ float4 maskwall(float4 v, bool lo, bool hi){
    if (lo) v.x = 0.0f;
    if (hi) v.w = 0.0f;
    return v;
}

__global__ __launch_bounds__(128, 4)
void rby2_kernel(const float4* __restrict__ s, float4* __restrict__ o)
{
    const int lane = threadIdx.x;                       // z chunk (4 z per lane)
    const int ty   = threadIdx.y;                       // 0..3 (each owns a y-pair)
    const int y0   = (blockIdx.x << 3) + (ty << 1);     // even row of the pair
    const int y1   = y0 + 1;
    const int x    = blockIdx.y;

    const unsigned long long pol = mk_policy();

    const int pxm = ((x + NX - 1) & (NX - 1)) * XS4;
    const int pc  = x * XS4;
    const int pxp = ((x + 1) & (NX - 1)) * XS4;

    const int iym  = pc + ((y0 + NY - 1) & (NY - 1)) * NZ4 + lane;
    const int i0   = pc + y0 * NZ4 + lane;
    const int i1   = pc + y1 * NZ4 + lane;
    const int iyp  = pc + ((y1 + 1) & (NY - 1)) * NZ4 + lane;
    const int ixm0 = pxm + y0 * NZ4 + lane;
    const int ixm1 = pxm + y1 * NZ4 + lane;
    const int ixp0 = pxp + y0 * NZ4 + lane;
    const int ixp1 = pxp + y1 * NZ4 + lane;

    const bool lo = (lane == 0);
    const bool hi = (lane == 31);

    float4 rinv0, rinv1;
    float4 dpdx0, dpdx1, dpdy0, dpdy1, dpdz0, dpdz1;
    float4 uxm0, uxm1, uxp0, uxp1;          // kept for u phase
    float4 uc0, uc1, vc0, vc1, wc0, wc1;    // advection velocities

    // ========= phase 1: rho + T -> rinv, pressure gradients, drou, dT =========
    {
        const float4 rym = ldg_el(s+3*FS4+iym, pol), r0 = ldg_el(s+3*FS4+i0, pol), r1 = ldg_el(s+3*FS4+i1, pol), ryp = ldg_el(s+3*FS4+iyp, pol);
        const float4 rxm0 = ldg_el(s+3*FS4+ixm0, pol), rxm1 = ldg_el(s+3*FS4+ixm1, pol);
        const float4 rxp0 = ldg_el(s+3*FS4+ixp0, pol), rxp1 = ldg_el(s+3*FS4+ixp1, pol);
        const float4 Tym = ldg_el(s+4*FS4+iym, pol), T0 = ldg_el(s+4*FS4+i0, pol), T1 = ldg_el(s+4*FS4+i1, pol), Typ = ldg_el(s+4*FS4+iyp, pol);
        const float4 Txm0 = ldg_el(s+4*FS4+ixm0, pol), Txm1 = ldg_el(s+4*FS4+ixm1, pol);
        const float4 Txp0 = ldg_el(s+4*FS4+ixp0, pol), Txp1 = ldg_el(s+4*FS4+ixp1, pol);

        rinv0 = inv4(r0);
        rinv1 = inv4(r1);

        dpdx0 = (rxp0 * Txp0 - rxm0 * Txm0) * (Rg * inv2dx);
        dpdx1 = (rxp1 * Txp1 - rxm1 * Txm1) * (Rg * inv2dx);
        dpdy0 = (r1  * T1  - rym * Tym) * (Rg * inv2dy);
        dpdy1 = (ryp * Typ - r0  * T0 ) * (Rg * inv2dy);
        const float4 p0 = r0 * T0;
        const float4 p1 = r1 * T1;
        dpdz0 = (zp_of(p0) - zm_of(p0)) * (Rg * inv2dz);
        dpdz1 = (zp_of(p1) - zm_of(p1)) * (Rg * inv2dz);

        // u x-neighbors for drou (kept live into the u phase)
        uxm0 = ldg_el(s+0*FS4+ixm0, pol); uxm1 = ldg_el(s+0*FS4+ixm1, pol);
        uxp0 = ldg_el(s+0*FS4+ixp0, pol); uxp1 = ldg_el(s+0*FS4+ixp1, pol);
        __stcs(&o[3*FS4 + i0], (rxm0 * uxm0 - rxp0 * uxp0) * inv2dx);
        __stcs(&o[3*FS4 + i1], (rxm1 * uxm1 - rxp1 * uxp1) * inv2dx);

        // advection velocities (centers)
        uc0 = ldg_el(s+0*FS4+i0, pol); uc1 = ldg_el(s+0*FS4+i1, pol);
        vc0 = ldg_el(s+1*FS4+i0, pol); vc1 = ldg_el(s+1*FS4+i1, pol);
        wc0 = ldg_el(s+2*FS4+i0, pol); wc1 = ldg_el(s+2*FS4+i1, pol);

        // dT (T fully resident)
        const float4 Tzm0 = zm_of(T0), Tzp0 = zp_of(T0);
        const float4 Tzm1 = zm_of(T1), Tzp1 = zp_of(T1);

        const float4 lapT0 = (Txp0 + Txm0 - T0*2.0f)*invdx2 + (T1 + Tym - T0*2.0f)*invdy2 + (Tzp0 + Tzm0 - T0*2.0f)*invdz2;
        const float4 advT0 = uc0*((Txp0 - Txm0)*inv2dx) + vc0*((T1 - Tym)*inv2dy) + wc0*((Tzp0 - Tzm0)*inv2dz);
        __stcs(&o[4*FS4 + i0], maskwall((lapT0 * kTco) * rinv0 - advT0, lo, hi));

        const float4 lapT1 = (Txp1 + Txm1 - T1*2.0f)*invdx2 + (Typ + T0 - T1*2.0f)*invdy2 + (Tzp1 + Tzm1 - T1*2.0f)*invdz2;
        const float4 advT1 = uc1*((Txp1 - Txm1)*inv2dx) + vc1*((Typ - T0)*inv2dy) + wc1*((Tzp1 - Tzm1)*inv2dz);
        __stcs(&o[4*FS4 + i1], maskwall((lapT1 * kTco) * rinv1 - advT1, lo, hi));
    }

    // ========= phase 2: u (x-neighbors already live; y-halo 2 loads) =========
    {
        const float4 uym = ldg_el(s+0*FS4+iym, pol), uyp = ldg_el(s+0*FS4+iyp, pol);
        const float4 uzm0 = zm_of(uc0), uzp0 = zp_of(uc0);
        const float4 uzm1 = zm_of(uc1), uzp1 = zp_of(uc1);

        const float4 lapU0 = (uxp0 + uxm0 - uc0*2.0f)*invdx2 + (uc1 + uym - uc0*2.0f)*invdy2 + (uzp0 + uzm0 - uc0*2.0f)*invdz2;
        const float4 advU0 = uc0*((uxp0 - uxm0)*inv2dx) + vc0*((uc1 - uym)*inv2dy) + wc0*((uzp0 - uzm0)*inv2dz);
        __stcs(&o[0*FS4 + i0], maskwall((lapU0 * MUc - dpdx0) * rinv0 - advU0, lo, hi));

        const float4 lapU1 = (uxp1 + uxm1 - uc1*2.0f)*invdx2 + (uyp + uc0 - uc1*2.0f)*invdy2 + (uzp1 + uzm1 - uc1*2.0f)*invdz2;
        const float4 advU1 = uc1*((uxp1 - uxm1)*inv2dx) + vc1*((uyp - uc0)*inv2dy) + wc1*((uzp1 - uzm1)*inv2dz);
        __stcs(&o[0*FS4 + i1], maskwall((lapU1 * MUc - dpdx1) * rinv1 - advU1, lo, hi));
    }

    // ========= phase 3: v =========
    {
        const float4 vym = ldg_el(s+1*FS4+iym, pol), vyp = ldg_el(s+1*FS4+iyp, pol);
        const float4 vxm0 = ldg_el(s+1*FS4+ixm0, pol), vxm1 = ldg_el(s+1*FS4+ixm1, pol);
        const float4 vxp0 = ldg_el(s+1*FS4+ixp0, pol), vxp1 = ldg_el(s+1*FS4+ixp1, pol);
        const float4 vzm0 = zm_of(vc0), vzp0 = zp_of(vc0);
        const float4 vzm1 = zm_of(vc1), vzp1 = zp_of(vc1);

        const float4 lapV0 = (vxp0 + vxm0 - vc0*2.0f)*invdx2 + (vc1 + vym - vc0*2.0f)*invdy2 + (vzp0 + vzm0 - vc0*2.0f)*invdz2;
        const float4 advV0 = uc0*((vxp0 - vxm0)*inv2dx) + vc0*((vc1 - vym)*inv2dy) + wc0*((vzp0 - vzm0)*inv2dz);
        __stcs(&o[1*FS4 + i0], maskwall((lapV0 * MUc - dpdy0) * rinv0 - advV0, lo, hi));

        const float4 lapV1 = (vxp1 + vxm1 - vc1*2.0f)*invdx2 + (vyp + vc0 - vc1*2.0f)*invdy2 + (vzp1 + vzm1 - vc1*2.0f)*invdz2;
        const float4 advV1 = uc1*((vxp1 - vxm1)*inv2dx) + vc1*((vyp - vc0)*inv2dy) + wc1*((vzp1 - vzm1)*inv2dz);
        __stcs(&o[1*FS4 + i1], maskwall((lapV1 * MUc - dpdy1) * rinv1 - advV1, lo, hi));
    }

    // ========= phase 4: w  ((-G*rho)/rho == -G) =========
    {
        const float4 wym = ldg_el(s+2*FS4+iym, pol), wyp = ldg_el(s+2*FS4+iyp, pol);
        const float4 wxm0 = ldg_el(s+2*FS4+ixm0, pol), wxm1 = ldg_el(s+2*FS4+ixm1, pol);
        const float4 wxp0 = ldg_el(s+2*FS4+ixp0, pol), wxp1 = ldg_el(s+2*FS4+ixp1, pol);
        const float4 wzm0 = zm_of(wc0), wzp0 = zp_of(wc0);
        const float4 wzm1 = zm_of(wc1), wzp1 = zp_of(wc1);

        const float4 lapW0 = (wxp0 + wxm0 - wc0*2.0f)*invdx2 + (wc1 + wym - wc0*2.0f)*invdy2 + (wzp0 + wzm0 - wc0*2.0f)*invdz2;
        const float4 advW0 = uc0*((wxp0 - wxm0)*inv2dx) + vc0*((wc1 - wym)*inv2dy) + wc0*((wzp0 - wzm0)*inv2dz);
        float4 dw0 = (lapW0 * MUc - dpdz0) * rinv0 - advW0;
        dw0 = make_float4(dw0.x - Gc, dw0.y - Gc, dw0.z - Gc, dw0.w - Gc);
        __stcs(&o[2*FS4 + i0], maskwall(dw0, lo, hi));

        const float4 lapW1 = (wxp1 + wxm1 - wc1*2.0f)*invdx2 + (wyp + wc0 - wc1*2.0f)*invdy2 + (wzp1 + wzm1 - wc1*2.0f)*invdz2;
        const float4 advW1 = uc1*((wxp1 - wxm1)*inv2dx) + vc1*((wyp - wc0)*inv2dy) + wc1*((wzp1 - wzm1)*inv2dz);
        float4 dw1 = (lapW1 * MUc - dpdz1) * rinv1 - advW1;
        dw1 = make_float4(dw1.x - Gc, dw1.y - Gc, dw1.z - Gc, dw1.w - Gc);
        __stcs(&o[2*FS4 + i1], maskwall(dw1, lo, hi));
    }

    // ========= phase 5: c (one-sided z at walls, NOT masked) =========
    {
        const float4 cym = ldg_el(s+5*FS4+iym, pol), c0 = ldg_el(s+5*FS4+i0, pol), c1 = ldg_el(s+5*FS4+i1, pol), cyp = ldg_el(s+5*FS4+iyp, pol);
        const float4 cxm0 = ldg_el(s+5*FS4+ixm0, pol), cxm1 = ldg_el(s+5*FS4+ixm1, pol);
        const float4 cxp0 = ldg_el(s+5*FS4+ixp0, pol), cxp1 = ldg_el(s+5*FS4+ixp1, pol);

        const float4 czm0 = zm_of(c0), czp0 = zp_of(c0);
        const float4 czm1 = zm_of(c1), czp1 = zp_of(c1);

        float4 dcdz0 = (czp0 - czm0) * inv2dz;
        float4 dcdz1 = (czp1 - czm1) * inv2dz;
        if (lo) {
            dcdz0.x = (-3.0f * c0.x + 4.0f * c0.y - c0.z) * inv2dz;
            dcdz1.x = (-3.0f * c1.x + 4.0f * c1.y - c1.z) * inv2dz;
        }
        if (hi) {
            dcdz0.w = ( 3.0f * c0.w - 4.0f * c0.z + c0.y) * inv2dz;
            dcdz1.w = ( 3.0f * c1.w - 4.0f * c1.z + c1.y) * inv2dz;
        }

        const float4 advC0 = uc0*((cxp0 - cxm0)*inv2dx) + vc0*((c1 - cym)*inv2dy) + wc0*dcdz0;
        __stcs(&o[5*FS4 + i0], make_float4(-advC0.x, -advC0.y, -advC0.z, -advC0.w));
        const float4 advC1 = uc1*((cxp1 - cxm1)*inv2dx) + vc1*((cyp - c0)*inv2dy) + wc1*dcdz1;
        __stcs(&o[5*FS4 + i1], make_float4(-advC1.x, -advC1.y, -advC1.z, -advC1.w));
    }
}
} // namespace

extern "C" void kernel_launch(void* const* d_in, const int* in_sizes, int n_in,
                              void* d_out, int out_size)
{
    const float4* s = (const float4*)d_in[0];
    float4* o = (float4*)d_out;
    dim3 block(32, 4, 1);               // 128 threads: 32 z-chunks × 4 y-pairs (8 rows)
    dim3 grid(NY / 8, NX, 1);           // 32 × 256 blocks
    rby2_kernel<<<grid, block>>>(s, o);
}

// round 16
// speedup vs baseline: 1.0310x; 1.0041x over previous
#include <cuda_runtime.h>

namespace {
constexpr int NX = 256, NY = 256, NZ = 128;
constexpr int NZ4 = NZ / 4, XS4 = NY * NZ4, FS4 = NX * XS4;

constexpr float CVc = 717.0f;
constexpr float MUc = 1.8e-5f, KTHc = 0.025f, Gc = 9.8f;
constexpr float Rg  = 287.0f;

constexpr double DXd = 1.0 / NX, DYd = 1.0 / NY, DZd = 1.0 / (NZ - 1);
constexpr float inv2dx = (float)(0.5 / DXd);
constexpr float inv2dy = (float)(0.5 / DYd);
constexpr float inv2dz = (float)(0.5 / DZd);
constexpr float invdx2 = (float)(1.0 / (DXd * DXd));
constexpr float invdy2 = (float)(1.0 / (DYd * DYd));
constexpr float invdz2 = (float)(1.0 / (DZd * DZd));
constexpr float kTco   = KTHc / CVc;

__device__ __forceinline__ float4 operator+(float4 a, float4 b){ return make_float4(a.x+b.x, a.y+b.y, a.z+b.z, a.w+b.w); }
__device__ __forceinline__ float4 operator-(float4 a, float4 b){ return make_float4(a.x-b.x, a.y-b.y, a.z-b.z, a.w-b.w); }
__device__ __forceinline__ float4 operator*(float4 a, float4 b){ return make_float4(a.x*b.x, a.y*b.y, a.z*b.z, a.w*b.w); }
__device__ __forceinline__ float4 operator*(float4 a, float s){ return make_float4(a.x*s, a.y*s, a.z*s, a.w*s); }
__device__ __forceinline__ float4 operator*(float s, float4 a){ return a * s; }

// L2 evict_last policy, fraction tuned so the protected set (~0.5 * 201MB) fits in 126MB L2
__device__ __forceinline__ unsigned long long mk_policy(){
    unsigned long long pol;
    asm("createpolicy.fractional.L2::evict_last.b64 %0, 0.5;" : "=l"(pol));
    return pol;
}
// input load: non-coherent, L2 evict_last via cache_hint (retain input lines in L2)
__device__ __forceinline__ float4 ldg_el(const float4* p, unsigned long long pol){
    float4 v;
    asm volatile("ld.global.nc.L2::cache_hint.v4.f32 {%0,%1,%2,%3}, [%4], %5;"
                 : "=f"(v.x), "=f"(v.y), "=f"(v.z), "=f"(v.w) : "l"(p), "l"(pol));
    return v;
}

__device__ __forceinline__ float4 zm_of(float4 a){
    float p = __shfl_up_sync(0xffffffffu, a.w, 1);
    return make_float4(p, a.x, a.y, a.z);
}
__device__ __forceinline__ float4 zp_of(float4 a){
    float n = __shfl_down_sync(0xffffffffu, a.x, 1);
    return make_float4(a.y, a.z, a.w, n);
}
__device__ __forceinline__ float4 inv4(float4 a){
    return make_float4(1.0f/a.x, 1.0f/a.y, 1.0f/a.z, 1.0f/a.w);
}
__device__ __forceinline__ float4 maskwall(float4 v, bool lo, bool hi){
    if (lo) v.x = 0.0f;
    if (hi) v.w = 0.0f;
    return v;
}

__global__ __launch_bounds__(128, 4)
void rby2_kernel(const float4* __restrict__ s, float4* __restrict__ o)
{
    const int lane = threadIdx.x;                       // z chunk (4 z per lane)
    const int ty   = threadIdx.y;                       // 0..3 (each owns a y-pair)
    const int y0   = (blockIdx.x << 3) + (ty << 1);     // even row of the pair
    const int y1   = y0 + 1;
    const int x    = blockIdx.y;

    const unsigned long long pol = mk_policy();

    const int pxm = ((x + NX - 1) & (NX - 1)) * XS4;
    const int pc  = x * XS4;
    const int pxp = ((x + 1) & (NX - 1)) * XS4;

    const int iym  = pc + ((y0 + NY - 1) & (NY - 1)) * NZ4 + lane;
    const int i0   = pc + y0 * NZ4 + lane;
    const int i1   = pc + y1 * NZ4 + lane;
    const int iyp  = pc + ((y1 + 1) & (NY - 1)) * NZ4 + lane;
    const int ixm0 = pxm + y0 * NZ4 + lane;
    const int ixm1 = pxm + y1 * NZ4 + lane;
    const int ixp0 = pxp + y0 * NZ4 + lane;
    const int ixp1 = pxp + y1 * NZ4 + lane;

    const bool lo = (lane == 0);
    const bool hi = (lane == 31);

    float4 rinv0, rinv1;
    float4 dpdx0, dpdx1, dpdy0, dpdy1, dpdz0, dpdz1;
    float4 uxm0, uxm1, uxp0, uxp1;          // kept for u phase
    float4 uc0, uc1, vc0, vc1, wc0, wc1;    // advection velocities

    // ========= phase 1: rho + T -> rinv, pressure gradients, drou, dT =========
    {
        const float4 rym = ldg_el(s+3*FS4+iym, pol), r0 = ldg_el(s+3*FS4+i0, pol), r1 = ldg_el(s+3*FS4+i1, pol), ryp = ldg_el(s+3*FS4+iyp, pol);
        const float4 rxm0 = ldg_el(s+3*FS4+ixm0, pol), rxm1 = ldg_el(s+3*FS4+ixm1, pol);
        const float4 rxp0 = ldg_el(s+3*FS4+ixp0, pol), rxp1 = ldg_el(s+3*FS4+ixp1, pol);
        const float4 Tym = ldg_el(s+4*FS4+iym, pol), T0 = ldg_el(s+4*FS4+i0, pol), T1 = ldg_el(s+4*FS4+i1, pol), Typ = ldg_el(s+4*FS4+iyp, pol);
        const float4 Txm0 = ldg_el(s+4*FS4+ixm0, pol), Txm1 = ldg_el(s+4*FS4+ixm1, pol);
        const float4 Txp0 = ldg_el(s+4*FS4+ixp0, pol), Txp1 = ldg_el(s+4*FS4+ixp1, pol);

        rinv0 = inv4(r0);
        rinv1 = inv4(r1);

        dpdx0 = (rxp0 * Txp0 - rxm0 * Txm0) * (Rg * inv2dx);
        dpdx1 = (rxp1 * Txp1 - rxm1 * Txm1) * (Rg * inv2dx);
        dpdy0 = (r1  * T1  - rym * Tym) * (Rg * inv2dy);
        dpdy1 = (ryp * Typ - r0  * T0 ) * (Rg * inv2dy);
        const float4 p0 = r0 * T0;
        const float4 p1 = r1 * T1;
        dpdz0 = (zp_of(p0) - zm_of(p0)) * (Rg * inv2dz);
        dpdz1 = (zp_of(p1) - zm_of(p1)) * (Rg * inv2dz);

        // u x-neighbors for drou (kept live into the u phase)
        uxm0 = ldg_el(s+0*FS4+ixm0, pol); uxm1 = ldg_el(s+0*FS4+ixm1, pol);
        uxp0 = ldg_el(s+0*FS4+ixp0, pol); uxp1 = ldg_el(s+0*FS4+ixp1, pol);
        __stcs(&o[3*FS4 + i0], (rxm0 * uxm0 - rxp0 * uxp0) * inv2dx);
        __stcs(&o[3*FS4 + i1], (rxm1 * uxm1 - rxp1 * uxp1) * inv2dx);

        // advection velocities (centers)
        uc0 = ldg_el(s+0*FS4+i0, pol); uc1 = ldg_el(s+0*FS4+i1, pol);
        vc0 = ldg_el(s+1*FS4+i0, pol); vc1 = ldg_el(s+1*FS4+i1, pol);
        wc0 = ldg_el(s+2*FS4+i0, pol); wc1 = ldg_el(s+2*FS4+i1, pol);

        // dT (T fully resident)
        const float4 Tzm0 = zm_of(T0), Tzp0 = zp_of(T0);
        const float4 Tzm1 = zm_of(T1), Tzp1 = zp_of(T1);

        const float4 lapT0 = (Txp0 + Txm0 - T0*2.0f)*invdx2 + (T1 + Tym - T0*2.0f)*invdy2 + (Tzp0 + Tzm0 - T0*2.0f)*invdz2;
        const float4 advT0 = uc0*((Txp0 - Txm0)*inv2dx) + vc0*((T1 - Tym)*inv2dy) + wc0*((Tzp0 - Tzm0)*inv2dz);
        __stcs(&o[4*FS4 + i0], maskwall((lapT0 * kTco) * rinv0 - advT0, lo, hi));

        const float4 lapT1 = (Txp1 + Txm1 - T1*2.0f)*invdx2 + (Typ + T0 - T1*2.0f)*invdy2 + (Tzp1 + Tzm1 - T1*2.0f)*invdz2;
        const float4 advT1 = uc1*((Txp1 - Txm1)*inv2dx) + vc1*((Typ - T0)*inv2dy) + wc1*((Tzp1 - Tzm1)*inv2dz);
        __stcs(&o[4*FS4 + i1], maskwall((lapT1 * kTco) * rinv1 - advT1, lo, hi));
    }

    // ========= phase 2: u (x-neighbors already live; y-halo 2 loads) =========
    {
        const float4 uym = ldg_el(s+0*FS4+iym, pol), uyp = ldg_el(s+0*FS4+iyp, pol);
        const float4 uzm0 = zm_of(uc0), uzp0 = zp_of(uc0);
        const float4 uzm1 = zm_of(uc1), uzp1 = zp_of(uc1);

        const float4 lapU0 = (uxp0 + uxm0 - uc0*2.0f)*invdx2 + (uc1 + uym - uc0*2.0f)*invdy2 + (uzp0 + uzm0 - uc0*2.0f)*invdz2;
        const float4 advU0 = uc0*((uxp0 - uxm0)*inv2dx) + vc0*((uc1 - uym)*inv2dy) + wc0*((uzp0 - uzm0)*inv2dz);
        __stcs(&o[0*FS4 + i0], maskwall((lapU0 * MUc - dpdx0) * rinv0 - advU0, lo, hi));

        const float4 lapU1 = (uxp1 + uxm1 - uc1*2.0f)*invdx2 + (uyp + uc0 - uc1*2.0f)*invdy2 + (uzp1 + uzm1 - uc1*2.0f)*invdz2;
        const float4 advU1 = uc1*((uxp1 - uxm1)*inv2dx) + vc1*((uyp - uc0)*inv2dy) + wc1*((uzp1 - uzm1)*inv2dz);
        __stcs(&o[0*FS4 + i1], maskwall((lapU1 * MUc - dpdx1) * rinv1 - advU1, lo, hi));
    }

    // ========= phase 3: v =========
    {
        const float4 vym = ldg_el(s+1*FS4+iym, pol), vyp = ldg_el(s+1*FS4+iyp, pol);
        const float4 vxm0 = ldg_el(s+1*FS4+ixm0, pol), vxm1 = ldg_el(s+1*FS4+ixm1, pol);
        const float4 vxp0 = ldg_el(s+1*FS4+ixp0, pol), vxp1 = ldg_el(s+1*FS4+ixp1, pol);
        const float4 vzm0 = zm_of(vc0), vzp0 = zp_of(vc0);
        const float4 vzm1 = zm_of(vc1), vzp1 = zp_of(vc1);

        const float4 lapV0 = (vxp0 + vxm0 - vc0*2.0f)*invdx2 + (vc1 + vym - vc0*2.0f)*invdy2 + (vzp0 + vzm0 - vc0*2.0f)*invdz2;
        const float4 advV0 = uc0*((vxp0 - vxm0)*inv2dx) + vc0*((vc1 - vym)*inv2dy) + wc0*((vzp0 - vzm0)*inv2dz);
        __stcs(&o[1*FS4 + i0], maskwall((lapV0 * MUc - dpdy0) * rinv0 - advV0, lo, hi));

        const float4 lapV1 = (vxp1 + vxm1 - vc1*2.0f)*invdx2 + (vyp + vc0 - vc1*2.0f)*invdy2 + (vzp1 + vzm1 - vc1*2.0f)*invdz2;
        const float4 advV1 = uc1*((vxp1 - vxm1)*inv2dx) + vc1*((vyp - vc0)*inv2dy) + wc1*((vzp1 - vzm1)*inv2dz);
        __stcs(&o[1*FS4 + i1], maskwall((lapV1 * MUc - dpdy1) * rinv1 - advV1, lo, hi));
    }

    // ========= phase 4: w  ((-G*rho)/rho == -G) =========
    {
        const float4 wym = ldg_el(s+2*FS4+iym, pol), wyp = ldg_el(s+2*FS4+iyp, pol);
        const float4 wxm0 = ldg_el(s+2*FS4+ixm0, pol), wxm1 = ldg_el(s+2*FS4+ixm1, pol);
        const float4 wxp0 = ldg_el(s+2*FS4+ixp0, pol), wxp1 = ldg_el(s+2*FS4+ixp1, pol);
        const float4 wzm0 = zm_of(wc0), wzp0 = zp_of(wc0);
        const float4 wzm1 = zm_of(wc1), wzp1 = zp_of(wc1);

        const float4 lapW0 = (wxp0 + wxm0 - wc0*2.0f)*invdx2 + (wc1 + wym - wc0*2.0f)*invdy2 + (wzp0 + wzm0 - wc0*2.0f)*invdz2;
        const float4 advW0 = uc0*((wxp0 - wxm0)*inv2dx) + vc0*((wc1 - wym)*inv2dy) + wc0*((wzp0 - wzm0)*inv2dz);
        float4 dw0 = (lapW0 * MUc - dpdz0) * rinv0 - advW0;
        dw0 = make_float4(dw0.x - Gc, dw0.y - Gc, dw0.z - Gc, dw0.w - Gc);
        __stcs(&o[2*FS4 + i0], maskwall(dw0, lo, hi));

        const float4 lapW1 = (wxp1 + wxm1 - wc1*2.0f)*invdx2 + (wyp + wc0 - wc1*2.0f)*invdy2 + (wzp1 + wzm1 - wc1*2.0f)*invdz2;
        const float4 advW1 = uc1*((wxp1 - wxm1)*inv2dx) + vc1*((wyp - wc0)*inv2dy) + wc1*((wzp1 - wzm1)*inv2dz);
        float4 dw1 = (lapW1 * MUc - dpdz1) * rinv1 - advW1;
        dw1 = make_float4(dw1.x - Gc, dw1.y - Gc, dw1.z - Gc, dw1.w - Gc);
        __stcs(&o[2*FS4 + i1], maskwall(dw1, lo, hi));
    }

    // ========= phase 5: c (one-sided z at walls, NOT masked) =========
    {
        const float4 cym = ldg_el(s+5*FS4+iym, pol), c0 = ldg_el(s+5*FS4+i0, pol), c1 = ldg_el(s+5*FS4+i1, pol), cyp = ldg_el(s+5*FS4+iyp, pol);
        const float4 cxm0 = ldg_el(s+5*FS4+ixm0, pol), cxm1 = ldg_el(s+5*FS4+ixm1, pol);
        const float4 cxp0 = ldg_el(s+5*FS4+ixp0, pol), cxp1 = ldg_el(s+5*FS4+ixp1, pol);

        const float4 czm0 = zm_of(c0), czp0 = zp_of(c0);
        const float4 czm1 = zm_of(c1), czp1 = zp_of(c1);

        float4 dcdz0 = (czp0 - czm0) * inv2dz;
        float4 dcdz1 = (czp1 - czm1) * inv2dz;
        if (lo) {
            dcdz0.x = (-3.0f * c0.x + 4.0f * c0.y - c0.z) * inv2dz;
            dcdz1.x = (-3.0f * c1.x + 4.0f * c1.y - c1.z) * inv2dz;
        }
        if (hi) {
            dcdz0.w = ( 3.0f * c0.w - 4.0f * c0.z + c0.y) * inv2dz;
            dcdz1.w = ( 3.0f * c1.w - 4.0f * c1.z + c1.y) * inv2dz;
        }

        const float4 advC0 = uc0*((cxp0 - cxm0)*inv2dx) + vc0*((c1 - cym)*inv2dy) + wc0*dcdz0;
        __stcs(&o[5*FS4 + i0], make_float4(-advC0.x, -advC0.y, -advC0.z, -advC0.w));
        const float4 advC1 = uc1*((cxp1 - cxm1)*inv2dx) + vc1*((cyp - c0)*inv2dy) + wc1*dcdz1;
        __stcs(&o[5*FS4 + i1], make_float4(-advC1.x, -advC1.y, -advC1.z, -advC1.w));
    }
}
} // namespace

extern "C" void kernel_launch(void* const* d_in, const int* in_sizes, int n_in,
                              void* d_out, int out_size)
{
    const float4* s = (const float4*)d_in[0];
    float4* o = (float4*)d_out;
    dim3 block(32, 4, 1);               // 128 threads: 32 z-chunks × 4 y-pairs (8 rows)
    dim3 grid(NY / 8, NX, 1);           // 32 × 256 blocks
    rby2_kernel<<<grid, block>>>(s, o);
}